// round 11
// baseline (speedup 1.0000x reference)
#include <cuda_runtime.h>

// Shapes (compile-time constants from the reference)
constexpr int B  = 2;
constexpr int L  = 24;
constexpr int R  = 8;
constexpr int C  = 32;
constexpr int H  = 48;
constexpr int WF = 49;

constexpr int RCW  = R * C * WF;        // 12,544   (A elements per (b,l))
constexpr int HW   = H * WF;            // 2,352
constexpr int RCHW = R * C * H * WF;    // 602,112  (u elements per (b,l))
constexpr int NA   = B * L * RCW;       // 602,112  (total A elements)
constexpr int NU   = B * L * RCHW;      // 28,901,376 (u elements per array)

// Precomputed transition coefficients A = decay * (cos, sin), interleaved
// float2. 4.8 MB -> L2-resident during the scan kernel. In-loop A LDGs are
// deliberately GLOBAL loads: measured (R3/R9 vs R6/R8) they add useful MLP.
__device__ float2 g_A[NA];

// ---------------------------------------------------------------------------
// Kernel 1: A[b,l,r,c,w] = exp(-nu*dt) * (cos(th*dt), sin(th*dt))
// Fast-math intrinsics; measured rel_err 2.5e-7 vs 1e-3 threshold.
// ---------------------------------------------------------------------------
__global__ void compute_A_kernel(const float* __restrict__ nu_rate,
                                 const float* __restrict__ theta_rate,
                                 const float* __restrict__ dt_seq) {
    int i = blockIdx.x * blockDim.x + threadIdx.x;
    if (i >= NA) return;
    int bl = i / RCW;                 // 0..B*L-1
    float dt = dt_seq[bl];
    float decay = __expf(-nu_rate[i] * dt);
    float s, c;
    __sincosf(theta_rate[i] * dt, &s, &c);
    g_A[i] = make_float2(decay * c, decay * s);
}

// ---------------------------------------------------------------------------
// Kernel 2: sequential complex recurrence over L in registers.
// EIGHT consecutive flat channels per thread (2x float4 per array per step):
// doubles per-warp MLP vs the 4-elem version (scan was latency-limited at
// occ 48% / DRAM 72%). launch_bounds(256,3): 85-reg cap, 3 CTAs/SM.
// Per-SM in-flight DRAM loads: 24 warps x 4 vs previous 32 x 2 -> +50%.
// ---------------------------------------------------------------------------
__global__ void __launch_bounds__(256, 3)
scan_kernel(const float4* __restrict__ ur,
            const float4* __restrict__ ui,
            float4* __restrict__ out) {
    const int t    = blockIdx.x * blockDim.x + threadIdx.x;  // 0 .. 150,527
    const int base = t * 8;                                  // global element
    const int b    = base / RCHW;
    const int flat = base - b * RCHW;                        // within batch

    // A index per lane (constant across l; stride RCW per step).
    int aidx[8];
    #pragma unroll
    for (int k = 0; k < 8; ++k) {
        int e = flat + k;
        aidx[k] = (e / HW) * WF + (e % HW) % WF;
    }

    float hr[8], hi[8];
    #pragma unroll
    for (int k = 0; k < 8; ++k) { hr[k] = 0.f; hi[k] = 0.f; }

    const int bL    = b * L;
    const int flat4 = flat >> 2;          // first of two float4 slots

    #pragma unroll
    for (int l = 0; l < L; ++l) {
        const int uoff4 = (bL + l) * (RCHW >> 2) + flat4;
        // Batch all four 16B loads up front (front-batched MLP).
        const float4 vr0 = __ldcs(&ur[uoff4]);
        const float4 vr1 = __ldcs(&ur[uoff4 + 1]);
        const float4 vi0 = __ldcs(&ui[uoff4]);
        const float4 vi1 = __ldcs(&ui[uoff4 + 1]);

        const int aoff = (bL + l) * RCW;
        float2 A[8];
        #pragma unroll
        for (int k = 0; k < 8; ++k) A[k] = g_A[aoff + aidx[k]];

        const float vrs[8] = {vr0.x, vr0.y, vr0.z, vr0.w,
                              vr1.x, vr1.y, vr1.z, vr1.w};
        const float vis[8] = {vi0.x, vi0.y, vi0.z, vi0.w,
                              vi1.x, vi1.y, vi1.z, vi1.w};

        #pragma unroll
        for (int k = 0; k < 8; ++k) {
            float nr = A[k].x * hr[k] - A[k].y * hi[k] + vrs[k];
            float ni = A[k].x * hi[k] + A[k].y * hr[k] + vis[k];
            hr[k] = nr; hi[k] = ni;
        }

        __stcs(&out[uoff4],     make_float4(hr[0], hr[1], hr[2], hr[3]));
        __stcs(&out[uoff4 + 1], make_float4(hr[4], hr[5], hr[6], hr[7]));
        __stcs(&out[(NU >> 2) + uoff4],     make_float4(hi[0], hi[1], hi[2], hi[3]));
        __stcs(&out[(NU >> 2) + uoff4 + 1], make_float4(hi[4], hi[5], hi[6], hi[7]));
    }
}

// ---------------------------------------------------------------------------
// kernel_launch: two launches, graph-capturable, no allocations.
// Inputs (metadata order): nu_rate, theta_rate, dt_seq, u_real, u_imag.
// Output: float32, shape (2, B, L, R, C, H, Wf) = 57,802,752 elements.
// ---------------------------------------------------------------------------
extern "C" void kernel_launch(void* const* d_in, const int* in_sizes, int n_in,
                              void* d_out, int out_size) {
    const float*  nu = (const float*)d_in[0];
    const float*  th = (const float*)d_in[1];
    const float*  dt = (const float*)d_in[2];
    const float4* ur = (const float4*)d_in[3];
    const float4* ui = (const float4*)d_in[4];
    float4* out = (float4*)d_out;

    compute_A_kernel<<<(NA + 255) / 256, 256>>>(nu, th, dt);

    constexpr int nthreads = (B * RCHW) / 8;   // 150,528
    scan_kernel<<<nthreads / 256, 256>>>(ur, ui, out);   // 588 blocks
}

// round 12
// speedup vs baseline: 1.2047x; 1.2047x over previous
#include <cuda_runtime.h>
#include <cuda_pipeline.h>

// Shapes (compile-time constants from the reference)
constexpr int B  = 2;
constexpr int L  = 24;
constexpr int R  = 8;
constexpr int C  = 32;
constexpr int H  = 48;
constexpr int WF = 49;

constexpr int RCW  = R * C * WF;        // 12,544   (A elements per (b,l))
constexpr int HW   = H * WF;            // 2,352
constexpr int RCHW = R * C * H * WF;    // 602,112  (u elements per (b,l))
constexpr int NA   = B * L * RCW;       // 602,112  (total A elements)
constexpr int NU   = B * L * RCHW;      // 28,901,376 (u elements per array)

constexpr int DEPTH = 5;                // cp.async ring depth (4 outstanding)

// Precomputed transition coefficients A = decay * (cos, sin), interleaved
// float2. 4.8 MB -> L2-resident during the scan kernel. In-loop A LDGs are
// deliberately GLOBAL loads: measured (R3/R9 vs R6/R8) they add useful MLP.
__device__ float2 g_A[NA];

// ---------------------------------------------------------------------------
// Kernel 1: A[b,l,r,c,w] = exp(-nu*dt) * (cos(th*dt), sin(th*dt))
// Fast-math intrinsics; measured rel_err 2.5e-7 vs 1e-3 threshold.
// ---------------------------------------------------------------------------
__global__ void compute_A_kernel(const float* __restrict__ nu_rate,
                                 const float* __restrict__ theta_rate,
                                 const float* __restrict__ dt_seq) {
    int i = blockIdx.x * blockDim.x + threadIdx.x;
    if (i >= NA) return;
    int bl = i / RCW;                 // 0..B*L-1
    float dt = dt_seq[bl];
    float decay = __expf(-nu_rate[i] * dt);
    float s, c;
    __sincosf(theta_rate[i] * dt, &s, &c);
    g_A[i] = make_float2(decay * c, decay * s);
}

// ---------------------------------------------------------------------------
// Kernel 2: R9 scan shape (4 elem/thread, 256 thr, 4 CTAs/SM, 1.99 waves)
// with the u stream moved onto a cp.async ring:
//   - thread t copies its own 16B (ur) + 16B (ui) per step into s_u*[st][t]
//     and is the only reader of that slot -> NO barriers needed.
//   - depth 5, steady state 4 outstanding commit-groups: ~4KB u in flight
//     per warp WITHOUT spending registers (the R10/R11 failure mode).
//   - cp.async 16B uses .cg (L2-only), preserving the read-once semantics.
// A loads stay as in-loop LDG.64 from L2-resident g_A (measured useful MLP).
// Tail: an empty commit-group is issued every iteration so wait_prior(4)
// keeps meaning "group l is complete" for all l.
// ---------------------------------------------------------------------------
__global__ void __launch_bounds__(256, 4)
scan_kernel(const float4* __restrict__ ur,
            const float4* __restrict__ ui,
            float4* __restrict__ out) {
    __shared__ float4 s_ur[DEPTH][256];   // 20,480 B
    __shared__ float4 s_ui[DEPTH][256];   // 20,480 B  (total 40 KB <= 48 KB static)

    const int tid  = threadIdx.x;
    const int t    = blockIdx.x * blockDim.x + tid;   // 0 .. 301,055
    const int base = t * 4;                           // global element index
    const int b    = base / RCHW;
    const int flat = base - b * RCHW;                 // within batch

    // A index per lane: a_flat = (e/HW)*WF + (e%WF); constant across l.
    int aidx0, aidx1, aidx2, aidx3;
    {
        int e0 = flat;
        aidx0 = (e0 / HW) * WF + (e0 % WF);
        int e1 = flat + 1;
        aidx1 = (e1 / HW) * WF + (e1 % WF);
        int e2 = flat + 2;
        aidx2 = (e2 / HW) * WF + (e2 % WF);
        int e3 = flat + 3;
        aidx3 = (e3 / HW) * WF + (e3 % WF);
    }

    const int bL    = b * L;
    const int flat4 = flat >> 2;

    // ---- Prologue: fill the ring (5 stages, one commit-group each) ----
    #pragma unroll
    for (int l = 0; l < DEPTH; ++l) {
        const int uoff4 = (bL + l) * (RCHW >> 2) + flat4;
        __pipeline_memcpy_async(&s_ur[l][tid], &ur[uoff4], 16);
        __pipeline_memcpy_async(&s_ui[l][tid], &ui[uoff4], 16);
        __pipeline_commit();
    }

    float hr0 = 0.f, hi0 = 0.f, hr1 = 0.f, hi1 = 0.f;
    float hr2 = 0.f, hi2 = 0.f, hr3 = 0.f, hi3 = 0.f;

    #pragma unroll
    for (int l = 0; l < L; ++l) {
        // Group l complete once at most DEPTH-1 groups remain outstanding
        // (one group was committed per l so far, incl. empty tail groups).
        __pipeline_wait_prior(DEPTH - 1);

        const int st = l % DEPTH;
        const float4 vr = s_ur[st][tid];
        const float4 vi = s_ui[st][tid];

        // Refill the slot we just consumed (self-owned: value already in regs).
        if (l + DEPTH < L) {
            const int noff4 = (bL + l + DEPTH) * (RCHW >> 2) + flat4;
            __pipeline_memcpy_async(&s_ur[st][tid], &ur[noff4], 16);
            __pipeline_memcpy_async(&s_ui[st][tid], &ui[noff4], 16);
        }
        __pipeline_commit();   // unconditional: keeps group accounting uniform

        const int aoff = (bL + l) * RCW;
        const float2 A0 = g_A[aoff + aidx0];
        const float2 A1 = g_A[aoff + aidx1];
        const float2 A2 = g_A[aoff + aidx2];
        const float2 A3 = g_A[aoff + aidx3];

        float nr, ni;
        nr = A0.x * hr0 - A0.y * hi0 + vr.x;
        ni = A0.x * hi0 + A0.y * hr0 + vi.x;
        hr0 = nr; hi0 = ni;

        nr = A1.x * hr1 - A1.y * hi1 + vr.y;
        ni = A1.x * hi1 + A1.y * hr1 + vi.y;
        hr1 = nr; hi1 = ni;

        nr = A2.x * hr2 - A2.y * hi2 + vr.z;
        ni = A2.x * hi2 + A2.y * hr2 + vi.z;
        hr2 = nr; hi2 = ni;

        nr = A3.x * hr3 - A3.y * hi3 + vr.w;
        ni = A3.x * hi3 + A3.y * hr3 + vi.w;
        hr3 = nr; hi3 = ni;

        const int uoff4 = (bL + l) * (RCHW >> 2) + flat4;
        __stcs(&out[uoff4],             make_float4(hr0, hr1, hr2, hr3)); // real
        __stcs(&out[(NU >> 2) + uoff4], make_float4(hi0, hi1, hi2, hi3)); // imag
    }
}

// ---------------------------------------------------------------------------
// kernel_launch: two launches, graph-capturable, no allocations.
// Inputs (metadata order): nu_rate, theta_rate, dt_seq, u_real, u_imag.
// Output: float32, shape (2, B, L, R, C, H, Wf) = 57,802,752 elements.
// ---------------------------------------------------------------------------
extern "C" void kernel_launch(void* const* d_in, const int* in_sizes, int n_in,
                              void* d_out, int out_size) {
    const float*  nu = (const float*)d_in[0];
    const float*  th = (const float*)d_in[1];
    const float*  dt = (const float*)d_in[2];
    const float4* ur = (const float4*)d_in[3];
    const float4* ui = (const float4*)d_in[4];
    float4* out = (float4*)d_out;

    compute_A_kernel<<<(NA + 255) / 256, 256>>>(nu, th, dt);

    constexpr int nthreads = (B * RCHW) / 4;   // 301,056
    scan_kernel<<<nthreads / 256, 256>>>(ur, ui, out);   // 1176 blocks
}

// round 13
// speedup vs baseline: 1.2290x; 1.0202x over previous
#include <cuda_runtime.h>

// Shapes (compile-time constants from the reference)
constexpr int B  = 2;
constexpr int L  = 24;
constexpr int R  = 8;
constexpr int C  = 32;
constexpr int H  = 48;
constexpr int WF = 49;

constexpr int RCW  = R * C * WF;        // 12,544   (A elements per (b,l))
constexpr int HW   = H * WF;            // 2,352
constexpr int RCHW = R * C * H * WF;    // 602,112  (u elements per (b,l))
constexpr int NA   = B * L * RCW;       // 602,112  (total A elements)
constexpr int NU   = B * L * RCHW;      // 28,901,376 (u elements per array)

// Precomputed transition coefficients A = decay * (cos, sin), interleaved
// float2. 4.8 MB -> L2-resident during the scan kernel. In-loop A LDGs are
// deliberately GLOBAL loads: measured (R3/R9 vs R6/R8/R12) every attempt to
// move them (smem staging, cp.async) regressed; they provide useful MLP.
__device__ float2 g_A[NA];

// ---------------------------------------------------------------------------
// Kernel 1: A[b,l,r,c,w] = exp(-nu*dt) * (cos(th*dt), sin(th*dt))
// Fast-math intrinsics; measured rel_err 2.5e-7 vs 1e-3 threshold.
// ---------------------------------------------------------------------------
__global__ void compute_A_kernel(const float* __restrict__ nu_rate,
                                 const float* __restrict__ theta_rate,
                                 const float* __restrict__ dt_seq) {
    int i = blockIdx.x * blockDim.x + threadIdx.x;
    if (i >= NA) return;
    int bl = i / RCW;                 // 0..B*L-1
    float dt = dt_seq[bl];
    float decay = __expf(-nu_rate[i] * dt);
    float s, c;
    __sincosf(theta_rate[i] * dt, &s, &c);
    g_A[i] = make_float2(decay * c, decay * s);
}

// ---------------------------------------------------------------------------
// Kernel 2: R9 scan, SINGLE change: __launch_bounds__(256, 5).
// R9 measured 54 regs / 4 CTAs / occ 48% / DRAM 72.1%. The occ->DRAM curve
// (33%->66.5, 48%->72) is still rising; 5 CTAs/SM needs 51 regs (ptxas must
// shave 3 — usually free). 40 warps/SM, +25% in-flight DRAM loads with zero
// added instructions (the R10/R11/R12 failure modes all added machinery).
// ---------------------------------------------------------------------------
__global__ void __launch_bounds__(256, 5)
scan_kernel(const float4* __restrict__ ur,
            const float4* __restrict__ ui,
            float4* __restrict__ out) {
    int t = blockIdx.x * blockDim.x + threadIdx.x;   // 0 .. 301,055
    int base = t * 4;                                 // global element index
    int b    = base / RCHW;                           // batch
    int flat = base - b * RCHW;                       // channel within batch

    // A index per lane: a_flat = (e/HW)*WF + (e%WF); constant across l
    // (stride RCW per step), so compute once.
    int aidx0, aidx1, aidx2, aidx3;
    {
        int e0 = flat;
        aidx0 = (e0 / HW) * WF + (e0 % WF);
        int e1 = flat + 1;
        aidx1 = (e1 / HW) * WF + (e1 % WF);
        int e2 = flat + 2;
        aidx2 = (e2 / HW) * WF + (e2 % WF);
        int e3 = flat + 3;
        aidx3 = (e3 / HW) * WF + (e3 % WF);
    }

    float hr0 = 0.f, hi0 = 0.f, hr1 = 0.f, hi1 = 0.f;
    float hr2 = 0.f, hi2 = 0.f, hr3 = 0.f, hi3 = 0.f;

    const int bL = b * L;
    const int flat4 = flat >> 2;

    #pragma unroll
    for (int l = 0; l < L; ++l) {
        const int uoff4 = (bL + l) * (RCHW >> 2) + flat4;  // float4 index
        const float4 vr = __ldcs(&ur[uoff4]);   // read-once: evict-first
        const float4 vi = __ldcs(&ui[uoff4]);

        const int aoff = (bL + l) * RCW;
        const float2 A0 = g_A[aoff + aidx0];
        const float2 A1 = g_A[aoff + aidx1];
        const float2 A2 = g_A[aoff + aidx2];
        const float2 A3 = g_A[aoff + aidx3];

        float nr, ni;
        nr = A0.x * hr0 - A0.y * hi0 + vr.x;
        ni = A0.x * hi0 + A0.y * hr0 + vi.x;
        hr0 = nr; hi0 = ni;

        nr = A1.x * hr1 - A1.y * hi1 + vr.y;
        ni = A1.x * hi1 + A1.y * hr1 + vi.y;
        hr1 = nr; hi1 = ni;

        nr = A2.x * hr2 - A2.y * hi2 + vr.z;
        ni = A2.x * hi2 + A2.y * hr2 + vi.z;
        hr2 = nr; hi2 = ni;

        nr = A3.x * hr3 - A3.y * hi3 + vr.w;
        ni = A3.x * hi3 + A3.y * hr3 + vi.w;
        hr3 = nr; hi3 = ni;

        __stcs(&out[uoff4],             make_float4(hr0, hr1, hr2, hr3)); // real half
        __stcs(&out[(NU >> 2) + uoff4], make_float4(hi0, hi1, hi2, hi3)); // imag half
    }
}

// ---------------------------------------------------------------------------
// kernel_launch: two launches, graph-capturable, no allocations.
// Inputs (metadata order): nu_rate, theta_rate, dt_seq, u_real, u_imag.
// Output: float32, shape (2, B, L, R, C, H, Wf) = 57,802,752 elements.
// ---------------------------------------------------------------------------
extern "C" void kernel_launch(void* const* d_in, const int* in_sizes, int n_in,
                              void* d_out, int out_size) {
    const float*  nu = (const float*)d_in[0];
    const float*  th = (const float*)d_in[1];
    const float*  dt = (const float*)d_in[2];
    const float4* ur = (const float4*)d_in[3];
    const float4* ui = (const float4*)d_in[4];
    float4* out = (float4*)d_out;

    compute_A_kernel<<<(NA + 255) / 256, 256>>>(nu, th, dt);

    constexpr int nthreads = (B * RCHW) / 4;   // 301,056
    scan_kernel<<<nthreads / 256, 256>>>(ur, ui, out);   // 1176 blocks
}

// round 14
// speedup vs baseline: 1.3102x; 1.0661x over previous
#include <cuda_runtime.h>

// Shapes (compile-time constants from the reference)
constexpr int B  = 2;
constexpr int L  = 24;
constexpr int R  = 8;
constexpr int C  = 32;
constexpr int H  = 48;
constexpr int WF = 49;

constexpr int RCW  = R * C * WF;        // 12,544   (A elements per (b,l))
constexpr int HW   = H * WF;            // 2,352
constexpr int RCHW = R * C * H * WF;    // 602,112  (u elements per (b,l))
constexpr int NA   = B * L * RCW;       // 602,112  (total A elements)
constexpr int NU   = B * L * RCHW;      // 28,901,376 (u elements per array)

// Precomputed transition coefficients A = decay * (cos, sin), interleaved
// float2. 4.8 MB -> L2-resident during the scan kernel. In-loop A LDGs stay
// as GLOBAL loads: every alternative (smem stage R6/R8, cp.async R12, reg
// capping R13) measured worse. 54-reg natural compile is the optimum: the
// binding resource is ptxas's front-batched load depth, not occupancy.
__device__ float2 g_A[NA];

// ---------------------------------------------------------------------------
// Kernel 1: A[b,l,r,c,w] = exp(-nu*dt) * (cos(th*dt), sin(th*dt))
// Fast-math intrinsics; measured rel_err 2.5e-7 vs 1e-3 threshold.
// Signals programmatic completion right after its g_A store so the PDL'd
// scan kernel can begin its (A-independent) prologue early.
// ---------------------------------------------------------------------------
__global__ void compute_A_kernel(const float* __restrict__ nu_rate,
                                 const float* __restrict__ theta_rate,
                                 const float* __restrict__ dt_seq) {
    int i = blockIdx.x * blockDim.x + threadIdx.x;
    if (i < NA) {
        int bl = i / RCW;                 // 0..B*L-1
        float dt = dt_seq[bl];
        float decay = __expf(-nu_rate[i] * dt);
        float s, c;
        __sincosf(theta_rate[i] * dt, &s, &c);
        g_A[i] = make_float2(decay * c, decay * s);
    }
    cudaTriggerProgrammaticLaunchCompletion();
}

// ---------------------------------------------------------------------------
// Kernel 2: R9 scan body VERBATIM (best measured: 70.5us, DRAM 72.1%,
// 54 regs natural). Single addition: cudaGridDependencySynchronize() after
// the A-independent prologue, so under PDL this kernel's launch + index
// math overlaps compute_A's execution. All g_A reads are after the sync.
// ---------------------------------------------------------------------------
__global__ void __launch_bounds__(256, 4)
scan_kernel(const float4* __restrict__ ur,
            const float4* __restrict__ ui,
            float4* __restrict__ out) {
    int t = blockIdx.x * blockDim.x + threadIdx.x;   // 0 .. 301,055
    int base = t * 4;                                 // global element index
    int b    = base / RCHW;                           // batch
    int flat = base - b * RCHW;                       // channel within batch

    // A index per lane: a_flat = (e/HW)*WF + (e%WF); constant across l
    // (stride RCW per step), so compute once.
    int aidx0, aidx1, aidx2, aidx3;
    {
        int e0 = flat;
        aidx0 = (e0 / HW) * WF + (e0 % WF);
        int e1 = flat + 1;
        aidx1 = (e1 / HW) * WF + (e1 % WF);
        int e2 = flat + 2;
        aidx2 = (e2 / HW) * WF + (e2 % WF);
        int e3 = flat + 3;
        aidx3 = (e3 / HW) * WF + (e3 % WF);
    }

    // Wait for compute_A's g_A writes (PDL). No-op cost if serialized.
    cudaGridDependencySynchronize();

    float hr0 = 0.f, hi0 = 0.f, hr1 = 0.f, hi1 = 0.f;
    float hr2 = 0.f, hi2 = 0.f, hr3 = 0.f, hi3 = 0.f;

    const int bL = b * L;
    const int flat4 = flat >> 2;

    #pragma unroll
    for (int l = 0; l < L; ++l) {
        const int uoff4 = (bL + l) * (RCHW >> 2) + flat4;  // float4 index
        const float4 vr = __ldcs(&ur[uoff4]);   // read-once: evict-first
        const float4 vi = __ldcs(&ui[uoff4]);

        const int aoff = (bL + l) * RCW;
        const float2 A0 = g_A[aoff + aidx0];
        const float2 A1 = g_A[aoff + aidx1];
        const float2 A2 = g_A[aoff + aidx2];
        const float2 A3 = g_A[aoff + aidx3];

        float nr, ni;
        nr = A0.x * hr0 - A0.y * hi0 + vr.x;
        ni = A0.x * hi0 + A0.y * hr0 + vi.x;
        hr0 = nr; hi0 = ni;

        nr = A1.x * hr1 - A1.y * hi1 + vr.y;
        ni = A1.x * hi1 + A1.y * hr1 + vi.y;
        hr1 = nr; hi1 = ni;

        nr = A2.x * hr2 - A2.y * hi2 + vr.z;
        ni = A2.x * hi2 + A2.y * hr2 + vi.z;
        hr2 = nr; hi2 = ni;

        nr = A3.x * hr3 - A3.y * hi3 + vr.w;
        ni = A3.x * hi3 + A3.y * hr3 + vi.w;
        hr3 = nr; hi3 = ni;

        __stcs(&out[uoff4],             make_float4(hr0, hr1, hr2, hr3)); // real half
        __stcs(&out[(NU >> 2) + uoff4], make_float4(hi0, hi1, hi2, hi3)); // imag half
    }
}

// ---------------------------------------------------------------------------
// kernel_launch: two launches; scan uses Programmatic Dependent Launch so
// its launch + prologue overlap compute_A. Graph-capturable (PDL edges are
// supported in stream capture), no allocations, no syncs.
// Inputs (metadata order): nu_rate, theta_rate, dt_seq, u_real, u_imag.
// ---------------------------------------------------------------------------
extern "C" void kernel_launch(void* const* d_in, const int* in_sizes, int n_in,
                              void* d_out, int out_size) {
    const float*  nu = (const float*)d_in[0];
    const float*  th = (const float*)d_in[1];
    const float*  dt = (const float*)d_in[2];
    const float4* ur = (const float4*)d_in[3];
    const float4* ui = (const float4*)d_in[4];
    float4* out = (float4*)d_out;

    compute_A_kernel<<<(NA + 255) / 256, 256>>>(nu, th, dt);

    constexpr int nthreads = (B * RCHW) / 4;   // 301,056
    cudaLaunchConfig_t cfg = {};
    cfg.gridDim  = dim3(nthreads / 256);       // 1176
    cfg.blockDim = dim3(256);
    cfg.stream   = 0;                          // same stream as <<<>>> above
    cudaLaunchAttribute attrs[1];
    attrs[0].id = cudaLaunchAttributeProgrammaticStreamSerialization;
    attrs[0].val.programmaticStreamSerializationAllowed = 1;
    cfg.attrs    = attrs;
    cfg.numAttrs = 1;
    cudaLaunchKernelEx(&cfg, scan_kernel, ur, ui, out);
}

// round 15
// speedup vs baseline: 1.3181x; 1.0060x over previous
#include <cuda_runtime.h>

// Shapes (compile-time constants from the reference)
constexpr int B  = 2;
constexpr int L  = 24;
constexpr int R  = 8;
constexpr int C  = 32;
constexpr int H  = 48;
constexpr int WF = 49;

constexpr int RCW  = R * C * WF;        // 12,544   (A elements per (b,l))
constexpr int HW   = H * WF;            // 2,352
constexpr int RCHW = R * C * H * WF;    // 602,112  (u elements per (b,l))
constexpr int NA   = B * L * RCW;       // 602,112  (total A elements)
constexpr int NU   = B * L * RCHW;      // 28,901,376 (u elements per array)

// Precomputed transition coefficients A = decay * (cos, sin), interleaved
// float2. 4.8 MB -> L2-resident during the scan kernel. In-loop A LDGs stay
// GLOBAL: every alternative (smem R6/R8, cp.async R12, reg-cap R13) lost.
__device__ float2 g_A[NA];

// ---------------------------------------------------------------------------
// Kernel 1: A[b,l,r,c,w] = exp(-nu*dt) * (cos(th*dt), sin(th*dt))
// Vectorized: 4 elements/thread (NA % 4 == 0), float4 in, 2x float4 out.
// A 4-element chunk never crosses a (b,l) row (RCW ... 12544 % 4 == 0), so
// one dt lookup per thread. Fast-math: measured rel_err 2.5e-7 vs 1e-3.
// ---------------------------------------------------------------------------
__global__ void compute_A_kernel(const float4* __restrict__ nu_rate,
                                 const float4* __restrict__ theta_rate,
                                 const float*  __restrict__ dt_seq) {
    int i4 = blockIdx.x * blockDim.x + threadIdx.x;   // float4 index
    if (i4 >= NA / 4) return;
    float dt = dt_seq[(i4 * 4) / RCW];
    const float4 nu = nu_rate[i4];
    const float4 th = theta_rate[i4];

    float4 lo, hi;   // interleaved (cos,sin) pairs
    float s, c;
    lo.x = __expf(-nu.x * dt); __sincosf(th.x * dt, &s, &c);
    lo.y = lo.x * s; lo.x = lo.x * c;
    lo.z = __expf(-nu.y * dt); __sincosf(th.y * dt, &s, &c);
    lo.w = lo.z * s; lo.z = lo.z * c;
    hi.x = __expf(-nu.z * dt); __sincosf(th.z * dt, &s, &c);
    hi.y = hi.x * s; hi.x = hi.x * c;
    hi.z = __expf(-nu.w * dt); __sincosf(th.w * dt, &s, &c);
    hi.w = hi.z * s; hi.z = hi.z * c;

    float4* dst = reinterpret_cast<float4*>(&g_A[i4 * 4]);
    dst[0] = lo;
    dst[1] = hi;
    cudaTriggerProgrammaticLaunchCompletion();
}

// ---------------------------------------------------------------------------
// Kernel 2: R9 scan with ONE structural change: TWO l-steps per unrolled
// iteration, all four u float4 loads issued up front. Doubles front-batched
// DRAM MLP (MLP_p1 2 -> 4) for +8 live regs (~62), staying under the
// 64-reg / 4-CTA boundary — occupancy and wave structure unchanged
// (the horizontal version R10/R11 paid 80 regs / 3 CTAs and lost).
// ---------------------------------------------------------------------------
__global__ void __launch_bounds__(256, 4)
scan_kernel(const float4* __restrict__ ur,
            const float4* __restrict__ ui,
            float4* __restrict__ out) {
    int t = blockIdx.x * blockDim.x + threadIdx.x;   // 0 .. 301,055
    int base = t * 4;                                 // global element index
    int b    = base / RCHW;                           // batch
    int flat = base - b * RCHW;                       // channel within batch

    // A index per lane: a_flat = (e/HW)*WF + (e%WF); constant across l.
    int aidx0, aidx1, aidx2, aidx3;
    {
        int e0 = flat;
        aidx0 = (e0 / HW) * WF + (e0 % WF);
        int e1 = flat + 1;
        aidx1 = (e1 / HW) * WF + (e1 % WF);
        int e2 = flat + 2;
        aidx2 = (e2 / HW) * WF + (e2 % WF);
        int e3 = flat + 3;
        aidx3 = (e3 / HW) * WF + (e3 % WF);
    }

    // Wait for compute_A's g_A writes (PDL; measured cost: none).
    cudaGridDependencySynchronize();

    float hr0 = 0.f, hi0 = 0.f, hr1 = 0.f, hi1 = 0.f;
    float hr2 = 0.f, hi2 = 0.f, hr3 = 0.f, hi3 = 0.f;

    const int bL = b * L;
    const int flat4 = flat >> 2;

    #pragma unroll
    for (int l = 0; l < L; l += 2) {
        const int uoffa = (bL + l    ) * (RCHW >> 2) + flat4;
        const int uoffb = (bL + l + 1) * (RCHW >> 2) + flat4;
        // Front-batch all four DRAM loads for the two steps.
        const float4 vra = __ldcs(&ur[uoffa]);
        const float4 via = __ldcs(&ui[uoffa]);
        const float4 vrb = __ldcs(&ur[uoffb]);
        const float4 vib = __ldcs(&ui[uoffb]);

        // ---- step l ----
        {
            const int aoff = (bL + l) * RCW;
            const float2 A0 = g_A[aoff + aidx0];
            const float2 A1 = g_A[aoff + aidx1];
            const float2 A2 = g_A[aoff + aidx2];
            const float2 A3 = g_A[aoff + aidx3];

            float nr, ni;
            nr = A0.x * hr0 - A0.y * hi0 + vra.x;
            ni = A0.x * hi0 + A0.y * hr0 + via.x;
            hr0 = nr; hi0 = ni;
            nr = A1.x * hr1 - A1.y * hi1 + vra.y;
            ni = A1.x * hi1 + A1.y * hr1 + via.y;
            hr1 = nr; hi1 = ni;
            nr = A2.x * hr2 - A2.y * hi2 + vra.z;
            ni = A2.x * hi2 + A2.y * hr2 + via.z;
            hr2 = nr; hi2 = ni;
            nr = A3.x * hr3 - A3.y * hi3 + vra.w;
            ni = A3.x * hi3 + A3.y * hr3 + via.w;
            hr3 = nr; hi3 = ni;

            __stcs(&out[uoffa],             make_float4(hr0, hr1, hr2, hr3));
            __stcs(&out[(NU >> 2) + uoffa], make_float4(hi0, hi1, hi2, hi3));
        }

        // ---- step l+1 ----
        {
            const int aoff = (bL + l + 1) * RCW;
            const float2 A0 = g_A[aoff + aidx0];
            const float2 A1 = g_A[aoff + aidx1];
            const float2 A2 = g_A[aoff + aidx2];
            const float2 A3 = g_A[aoff + aidx3];

            float nr, ni;
            nr = A0.x * hr0 - A0.y * hi0 + vrb.x;
            ni = A0.x * hi0 + A0.y * hr0 + vib.x;
            hr0 = nr; hi0 = ni;
            nr = A1.x * hr1 - A1.y * hi1 + vrb.y;
            ni = A1.x * hi1 + A1.y * hr1 + vib.y;
            hr1 = nr; hi1 = ni;
            nr = A2.x * hr2 - A2.y * hi2 + vrb.z;
            ni = A2.x * hi2 + A2.y * hr2 + vib.z;
            hr2 = nr; hi2 = ni;
            nr = A3.x * hr3 - A3.y * hi3 + vrb.w;
            ni = A3.x * hi3 + A3.y * hr3 + vib.w;
            hr3 = nr; hi3 = ni;

            __stcs(&out[uoffb],             make_float4(hr0, hr1, hr2, hr3));
            __stcs(&out[(NU >> 2) + uoffb], make_float4(hi0, hi1, hi2, hi3));
        }
    }
}

// ---------------------------------------------------------------------------
// kernel_launch: two launches (scan via PDL), graph-capturable, no allocs.
// Inputs (metadata order): nu_rate, theta_rate, dt_seq, u_real, u_imag.
// ---------------------------------------------------------------------------
extern "C" void kernel_launch(void* const* d_in, const int* in_sizes, int n_in,
                              void* d_out, int out_size) {
    const float4* nu = (const float4*)d_in[0];
    const float4* th = (const float4*)d_in[1];
    const float*  dt = (const float*)d_in[2];
    const float4* ur = (const float4*)d_in[3];
    const float4* ui = (const float4*)d_in[4];
    float4* out = (float4*)d_out;

    compute_A_kernel<<<(NA / 4 + 255) / 256, 256>>>(nu, th, dt);

    constexpr int nthreads = (B * RCHW) / 4;   // 301,056
    cudaLaunchConfig_t cfg = {};
    cfg.gridDim  = dim3(nthreads / 256);       // 1176
    cfg.blockDim = dim3(256);
    cfg.stream   = 0;
    cudaLaunchAttribute attrs[1];
    attrs[0].id = cudaLaunchAttributeProgrammaticStreamSerialization;
    attrs[0].val.programmaticStreamSerializationAllowed = 1;
    cfg.attrs    = attrs;
    cfg.numAttrs = 1;
    cudaLaunchKernelEx(&cfg, scan_kernel, ur, ui, out);
}